// round 8
// baseline (speedup 1.0000x reference)
#include <cuda_runtime.h>
#include <cstdint>

#define F_IN   8192
#define F_OUT  16384
#define BATCH  32
#define HEADS  512

// Scratch (static __device__ — allocation-free per harness rules)
__device__ float g_xr[BATCH * F_IN];    // tf32(RNA)-rounded x
__device__ float g_q[BATCH * F_OUT];
__device__ float g_k[BATCH * F_OUT];
__device__ float g_v[BATCH * F_OUT];
__device__ float g_rzt[BATCH * 32 * 32]; // 1/Z transposed: [b][j][i]

__device__ __forceinline__ uint32_t tf32_rna(float f) {
    uint32_t u;
    asm("cvt.rna.tf32.f32 %0, %1;" : "=r"(u) : "f"(f));
    return u;
}

__device__ __forceinline__ float gelu_exact(float v) {
    return 0.5f * v * (1.0f + erff(v * 0.70710678118654752f));
}

// ---------------------------------------------------------------------------
// Kernel 0: pre-round x to tf32 (RNA) once. Vectorized float4.
// ---------------------------------------------------------------------------
__global__ void round_x_kernel(const float4* __restrict__ x) {
    int i = blockIdx.x * blockDim.x + threadIdx.x;
    float4 v = x[i];
    float4 o;
    o.x = __uint_as_float(tf32_rna(v.x));
    o.y = __uint_as_float(tf32_rna(v.y));
    o.z = __uint_as_float(tf32_rna(v.z));
    o.w = __uint_as_float(tf32_rna(v.w));
    reinterpret_cast<float4*>(g_xr)[i] = o;
}

// ---------------------------------------------------------------------------
// Kernel 1: QKV GEMM, transposed: D^T[m][b] = sum_k W[m][k]*x[b][k]
//   A (M-side) = W  : streamed, coalesced cp.async -> SMEM (read once)
//   B (N-side) = x^T: tiny, staged per chunk (pre-rounded; L2-resident)
// CTA: 128 thr / 4 warps, M-tile 64 (warp m16n32), N=32, K-chunk 32,
// FIVE buffers (15360 B each -> same 76800 B/CTA as the proven occ-3 config).
// Pipeline: 4 chunks in flight, ONE barrier per chunk, refill issued BEFORE
// compute: at iter c, wait_group 3 => chunk c landed; barrier also proves
// buf (c+4)%5 == (c-1)%5 was fully consumed last iter -> stage c+4 into it.
// k-permutation inside each k8 (logical tq -> phys 2tq, tq+4 -> 2tq+1) on
// BOTH operands => aligned LDS.64 fragments, conflict-free (RS=40; the
// LDS.64 two-phase split keeps banks 8g+2tq distinct per phase).
// ---------------------------------------------------------------------------
#define MMA_TF32(d, a0,a1,a2,a3, b0,b1)                                     \
    asm volatile("mma.sync.aligned.m16n8k8.row.col.f32.tf32.tf32.f32 "      \
        "{%0,%1,%2,%3}, {%4,%5,%6,%7}, {%8,%9}, {%0,%1,%2,%3};"             \
        : "+f"(d[0]), "+f"(d[1]), "+f"(d[2]), "+f"(d[3])                    \
        : "r"(a0), "r"(a1), "r"(a2), "r"(a3), "r"(b0), "r"(b1))

#define KC        32            // K-chunk
#define RS        40            // row stride in floats (32 + 8 pad)
#define MT        64            // CTA M-tile (rows of W)
#define NSTAGE    5
#define WSF       (MT * RS)     // 2560 floats per W stage
#define XSF       (BATCH * RS)  // 1280 floats per x stage
#define STAGEF    (WSF + XSF)   // 3840 floats = 15360 B per stage
#define SMEM_BYTES (NSTAGE * STAGEF * 4)   // 76800 B

__device__ __forceinline__ void cp16(float* dst, const float* src) {
    uint32_t d = (uint32_t)__cvta_generic_to_shared(dst);
    asm volatile("cp.async.cg.shared.global [%0], [%1], 16;" :: "r"(d), "l"(src));
}

__global__ __launch_bounds__(128, 3)
void qkv_gemm_kernel(const float* __restrict__ Wq, const float* __restrict__ bq,
                     const float* __restrict__ Wk, const float* __restrict__ bk,
                     const float* __restrict__ Wv, const float* __restrict__ bv) {
    extern __shared__ float smem[];

    const float* W; const float* bias; float* out;
    if (blockIdx.y == 0)      { W = Wq; bias = bq; out = g_q; }
    else if (blockIdx.y == 1) { W = Wk; bias = bk; out = g_k; }
    else                      { W = Wv; bias = bv; out = g_v; }

    const int tid  = threadIdx.x;
    const int warp = tid >> 5;
    const int lane = tid & 31;
    const int g    = lane >> 2;       // groupID (0..7)
    const int tq   = lane & 3;        // thread-in-group (0..3)
    const int mb   = blockIdx.x * MT; // CTA's first W row

    float acc[4][4];                  // [n-tile(batch/8)][frag], warp tile m16n32
    #pragma unroll
    for (int b = 0; b < 4; b++)
        #pragma unroll
        for (int r = 0; r < 4; r++) acc[b][r] = 0.0f;

    // stage one K-chunk: W tile 64x32 + x tile 32x32, both coalesced
    auto stage = [&](int s, int c) {
        float* ws = smem + s * STAGEF;
        float* xs = ws + WSF;
        const int kc = c * KC;
        #pragma unroll
        for (int r = 0; r < 4; r++) {
            int idx = tid + r * 128;            // 512 float4
            int row = idx >> 3;
            int c4  = idx & 7;
            cp16(&ws[row * RS + c4 * 4],
                 W + (size_t)(mb + row) * F_IN + kc + c4 * 4);
        }
        #pragma unroll
        for (int r = 0; r < 2; r++) {
            int idx = tid + r * 128;            // 256 float4
            int b   = idx >> 3;
            int c4  = idx & 7;
            cp16(&xs[b * RS + c4 * 4],
                 g_xr + (size_t)b * F_IN + kc + c4 * 4);
        }
        asm volatile("cp.async.commit_group;");
    };

    stage(0, 0); stage(1, 1); stage(2, 2); stage(3, 3);

    const int NCHUNK = F_IN / KC;      // 256
    for (int c = 0; c < NCHUNK; c++) {
        const int rem = NCHUNK - 1 - c;
        if (rem >= 3)      asm volatile("cp.async.wait_group 3;");
        else if (rem == 2) asm volatile("cp.async.wait_group 2;");
        else if (rem == 1) asm volatile("cp.async.wait_group 1;");
        else               asm volatile("cp.async.wait_group 0;");
        __syncthreads();               // chunk c visible; buf (c+4)%5 free

        if (c + 4 < NCHUNK) stage((c + 4) % NSTAGE, c + 4);

        const float* ws = smem + (c % NSTAGE) * STAGEF;
        const float* xs = ws + WSF;

        #pragma unroll
        for (int s = 0; s < 4; s++) {
            const int kp = 8 * s + 2 * tq;    // physical k offset in chunk

            // A (W) fragments: one m16 subtile, rows warp*16 + {g, g+8}
            const int r0 = warp * 16 + g;
            float2 lo = *reinterpret_cast<const float2*>(&ws[r0 * RS + kp]);
            float2 hi = *reinterpret_cast<const float2*>(&ws[(r0 + 8) * RS + kp]);
            uint32_t A0 = tf32_rna(lo.x);   // (m=g,   k'=tq)
            uint32_t A1 = tf32_rna(hi.x);   // (m=g+8, k'=tq)
            uint32_t A2 = tf32_rna(lo.y);   // (m=g,   k'=tq+4)
            uint32_t A3 = tf32_rna(hi.y);   // (m=g+8, k'=tq+4)

            // B (x^T) fragments: n = batch, 4 n-tiles of 8 (already tf32)
            float2 bvf[4];
            #pragma unroll
            for (int j = 0; j < 4; j++)
                bvf[j] = *reinterpret_cast<const float2*>(&xs[(j * 8 + g) * RS + kp]);

            #pragma unroll
            for (int j = 0; j < 4; j++)
                MMA_TF32(acc[j], A0, A1, A2, A3,
                         __float_as_uint(bvf[j].x), __float_as_uint(bvf[j].y));
        }
    }

    // Epilogue: bias + exact GELU, store transposed into [batch][F_OUT]
    {
        const int r0 = mb + warp * 16 + g;             // output feature index
        const float bia0 = bias[r0];
        const float bia1 = bias[r0 + 8];
        #pragma unroll
        for (int j = 0; j < 4; j++) {
            const int bt = j * 8 + 2 * tq;             // batch index
            out[(size_t)bt       * F_OUT + r0    ] = gelu_exact(acc[j][0] + bia0);
            out[(size_t)(bt + 1) * F_OUT + r0    ] = gelu_exact(acc[j][1] + bia0);
            out[(size_t)bt       * F_OUT + r0 + 8] = gelu_exact(acc[j][2] + bia1);
            out[(size_t)(bt + 1) * F_OUT + r0 + 8] = gelu_exact(acc[j][3] + bia1);
        }
    }
}

// ---------------------------------------------------------------------------
// Kernel 2: softmax denominators over the HEADS axis (bias cancels).
// rZt[b][j][i] = 1 / sum_h exp(c * q[b,h,i] * k[b,h,j])
// One-shot staging (k full 64KB + q slice 16KB), barrier-free 512-h loop.
// Same h accumulation order as before -> bitwise-identical z.
// ---------------------------------------------------------------------------
#define ATTN_SCALE 0.17677669529663687f   // 1/sqrt(32)
#define Z_SMEM (512 * 8 * 4 + 512 * 32 * 4)   // 81920 B

__global__ void attn_z_kernel() {
    extern __shared__ float zsm[];
    float* qs = zsm;              // [512][8]
    float* ks = zsm + 512 * 8;    // [512][32]

    const int b  = blockIdx.x;
    const int iq = blockIdx.y;
    const int tid = threadIdx.x;
    const int il  = tid >> 5;
    const int j   = tid & 31;
    const int i   = iq * 8 + il;

    const float4* __restrict__ qb4 = (const float4*)(g_q + (size_t)b * F_OUT);
    const float4* __restrict__ kb4 = (const float4*)(g_k + (size_t)b * F_OUT);

    // ks = k[b] verbatim (same layout): 4096 float4
    #pragma unroll
    for (int r = 0; r < 16; r++) {
        int idx = tid + r * 256;
        ((float4*)ks)[idx] = kb4[idx];
    }
    // qs[h][0..7] = q[b][h*32 + iq*8 .. +8]: 1024 float4
    #pragma unroll
    for (int r = 0; r < 4; r++) {
        int idx = tid + r * 256;
        int h = idx >> 1, u = idx & 1;
        ((float4*)qs)[idx] = qb4[h * 8 + iq * 2 + u];
    }
    __syncthreads();

    float z = 0.0f;
    #pragma unroll 8
    for (int h = 0; h < 512; h++)
        z += __expf(ATTN_SCALE * qs[h * 8 + il] * ks[h * 32 + j]);

    g_rzt[(size_t)b * 1024 + j * 32 + i] = 1.0f / z;
}

// ---------------------------------------------------------------------------
// Kernel 3: out[b,h,i] = sum_j exp(c*q_i*k_j) * rZ[b,i,j] * v[b,h,j]
// (k,v) staged in SMEM as float2 (LDS.64 broadcast per j),
// rz tile staged in SMEM.
// ---------------------------------------------------------------------------
__global__ void attn_o_kernel(float* __restrict__ out) {
    __shared__ float2 kvs[8][32];
    __shared__ float  rzs[1024];

    const int b    = blockIdx.y;
    const int tid  = threadIdx.x;
    const int wl   = tid >> 5;
    const int lane = tid & 31;
    const int h    = blockIdx.x * 8 + wl;

    const size_t base = (size_t)b * F_OUT + (size_t)h * 32;

    {
        float kk = g_k[base + lane];
        float vv = g_v[base + lane];
        kvs[wl][lane] = make_float2(kk, vv);
        #pragma unroll
        for (int r = 0; r < 4; r++)
            rzs[tid + r * 256] = g_rzt[(size_t)b * 1024 + tid + r * 256];
    }
    const float qv = g_q[base + lane] * ATTN_SCALE;
    __syncthreads();

    float accv = 0.0f;
    #pragma unroll
    for (int j = 0; j < 32; j++) {
        float2 kv = kvs[wl][j];                 // LDS.64 broadcast
        accv += __expf(qv * kv.x) * kv.y * rzs[j * 32 + lane];
    }
    out[((size_t)b * HEADS + h) * 32 + lane] = accv;
}

// ---------------------------------------------------------------------------
extern "C" void kernel_launch(void* const* d_in, const int* in_sizes, int n_in,
                              void* d_out, int out_size) {
    const float* x  = (const float*)d_in[0];
    const float* Wq = (const float*)d_in[1];
    const float* bq = (const float*)d_in[2];
    const float* Wk = (const float*)d_in[3];
    const float* bk = (const float*)d_in[4];
    const float* Wv = (const float*)d_in[5];
    const float* bv = (const float*)d_in[6];
    // d_in[7] (tw): constant along softmax axis (heads) -> cancels; unused.
    (void)in_sizes; (void)n_in; (void)out_size;

    cudaFuncSetAttribute(qkv_gemm_kernel,
                         cudaFuncAttributeMaxDynamicSharedMemorySize, SMEM_BYTES);
    cudaFuncSetAttribute(attn_z_kernel,
                         cudaFuncAttributeMaxDynamicSharedMemorySize, Z_SMEM);

    round_x_kernel<<<256, 256>>>((const float4*)x);
    qkv_gemm_kernel<<<dim3(F_OUT / MT, 3), 128, SMEM_BYTES>>>(Wq, bq, Wk, bk, Wv, bv);
    attn_z_kernel<<<dim3(32, 4), 256, Z_SMEM>>>();
    attn_o_kernel<<<dim3(64, 32), 256>>>((float*)d_out);
}

// round 9
// speedup vs baseline: 1.0472x; 1.0472x over previous
#include <cuda_runtime.h>
#include <cstdint>

#define F_IN   8192
#define F_OUT  16384
#define BATCH  32
#define HEADS  512

// Scratch (static __device__ — allocation-free per harness rules)
__device__ float g_xr[BATCH * F_IN];    // tf32(RNA)-rounded x
__device__ float g_q[BATCH * F_OUT];
__device__ float g_k[BATCH * F_OUT];
__device__ float g_v[BATCH * F_OUT];
__device__ float g_rzt[BATCH * 32 * 32]; // 1/Z transposed: [b][j][i]

__device__ __forceinline__ uint32_t tf32_rna(float f) {
    uint32_t u;
    asm("cvt.rna.tf32.f32 %0, %1;" : "=r"(u) : "f"(f));
    return u;
}

__device__ __forceinline__ float gelu_exact(float v) {
    return 0.5f * v * (1.0f + erff(v * 0.70710678118654752f));
}

// ---------------------------------------------------------------------------
// Kernel 0: pre-round x to tf32 (RNA) once. Vectorized float4.
// ---------------------------------------------------------------------------
__global__ void round_x_kernel(const float4* __restrict__ x) {
    int i = blockIdx.x * blockDim.x + threadIdx.x;
    float4 v = x[i];
    float4 o;
    o.x = __uint_as_float(tf32_rna(v.x));
    o.y = __uint_as_float(tf32_rna(v.y));
    o.z = __uint_as_float(tf32_rna(v.z));
    o.w = __uint_as_float(tf32_rna(v.w));
    reinterpret_cast<float4*>(g_xr)[i] = o;
}

// ---------------------------------------------------------------------------
// Kernel 1: QKV GEMM, transposed: D^T[m][b] = sum_k W[m][k]*x[b][k]
//   A (M-side) = W  : streamed, coalesced cp.async -> SMEM (read once)
//   B (N-side) = x^T: tiny, staged per chunk (pre-rounded to tf32)
// R5-proven pipeline: 3 stages, wait_group 2 steady-state, stage AFTER
// compute. ONLY change vs R5: 256 threads / 8 warps on the same MT=128 tile
// (warp tile m16n32) -> 24 warps/SM at occ 3 for 2x latency hiding
// (R6 profile: DRAM 73%, issue 54%, occ 15.5% -> latency-bound, not BW).
// k-permutation inside each k8 (logical tq -> phys 2tq, tq+4 -> 2tq+1) on
// BOTH operands => aligned LDS.64 fragments, conflict-free (RS=40 pad).
// ---------------------------------------------------------------------------
#define MMA_TF32(d, a0,a1,a2,a3, b0,b1)                                     \
    asm volatile("mma.sync.aligned.m16n8k8.row.col.f32.tf32.tf32.f32 "      \
        "{%0,%1,%2,%3}, {%4,%5,%6,%7}, {%8,%9}, {%0,%1,%2,%3};"             \
        : "+f"(d[0]), "+f"(d[1]), "+f"(d[2]), "+f"(d[3])                    \
        : "r"(a0), "r"(a1), "r"(a2), "r"(a3), "r"(b0), "r"(b1))

#define KC        32            // K-chunk
#define RS        40            // row stride in floats (32 + 8 pad)
#define MT        128           // CTA M-tile (rows of W)
#define NSTAGE    3
#define WSF       (MT * RS)     // 5120 floats per W stage
#define XSF       (BATCH * RS)  // 1280 floats per x stage
#define STAGEF    (WSF + XSF)   // 6400 floats per stage
#define SMEM_BYTES (NSTAGE * STAGEF * 4)   // 76800 B

__device__ __forceinline__ void cp16(float* dst, const float* src) {
    uint32_t d = (uint32_t)__cvta_generic_to_shared(dst);
    asm volatile("cp.async.cg.shared.global [%0], [%1], 16;" :: "r"(d), "l"(src));
}

__global__ __launch_bounds__(256, 3)
void qkv_gemm_kernel(const float* __restrict__ Wq, const float* __restrict__ bq,
                     const float* __restrict__ Wk, const float* __restrict__ bk,
                     const float* __restrict__ Wv, const float* __restrict__ bv) {
    extern __shared__ float smem[];

    const float* W; const float* bias; float* out;
    if (blockIdx.y == 0)      { W = Wq; bias = bq; out = g_q; }
    else if (blockIdx.y == 1) { W = Wk; bias = bk; out = g_k; }
    else                      { W = Wv; bias = bv; out = g_v; }

    const int tid  = threadIdx.x;
    const int warp = tid >> 5;
    const int lane = tid & 31;
    const int g    = lane >> 2;       // groupID (0..7)
    const int tq   = lane & 3;        // thread-in-group (0..3)
    const int mb   = blockIdx.x * MT; // CTA's first W row

    float acc[4][4];                  // [n-tile(batch/8)][frag], warp tile m16n32
    #pragma unroll
    for (int b = 0; b < 4; b++)
        #pragma unroll
        for (int r = 0; r < 4; r++) acc[b][r] = 0.0f;

    // stage one K-chunk: W tile 128x32 + x tile 32x32, both coalesced
    auto stage = [&](int s, int c) {
        float* ws = smem + s * STAGEF;
        float* xs = ws + WSF;
        const int kc = c * KC;
        #pragma unroll
        for (int r = 0; r < 4; r++) {
            int idx = tid + r * 256;            // 1024 float4
            int row = idx >> 3;
            int c4  = idx & 7;
            cp16(&ws[row * RS + c4 * 4],
                 W + (size_t)(mb + row) * F_IN + kc + c4 * 4);
        }
        {
            int b  = tid >> 3;                  // 256 float4
            int c4 = tid & 7;
            cp16(&xs[b * RS + c4 * 4],
                 g_xr + (size_t)b * F_IN + kc + c4 * 4);
        }
        asm volatile("cp.async.commit_group;");
    };

    stage(0, 0); stage(1, 1); stage(2, 2);

    const int NCHUNK = F_IN / KC;     // 256
    for (int c = 0; c < NCHUNK; c++) {
        const int rem = NCHUNK - 1 - c;
        if (rem >= 2)      asm volatile("cp.async.wait_group 2;");
        else if (rem == 1) asm volatile("cp.async.wait_group 1;");
        else               asm volatile("cp.async.wait_group 0;");
        __syncthreads();

        const float* ws = smem + (c % NSTAGE) * STAGEF;
        const float* xs = ws + WSF;

        #pragma unroll
        for (int s = 0; s < 4; s++) {
            const int kp = 8 * s + 2 * tq;    // physical k offset in chunk

            // A (W) fragments: one m16 subtile, rows warp*16 + {g, g+8}
            const int r0 = warp * 16 + g;
            float2 lo = *reinterpret_cast<const float2*>(&ws[r0 * RS + kp]);
            float2 hi = *reinterpret_cast<const float2*>(&ws[(r0 + 8) * RS + kp]);
            uint32_t A0 = tf32_rna(lo.x);   // (m=g,   k'=tq)
            uint32_t A1 = tf32_rna(hi.x);   // (m=g+8, k'=tq)
            uint32_t A2 = tf32_rna(lo.y);   // (m=g,   k'=tq+4)
            uint32_t A3 = tf32_rna(hi.y);   // (m=g+8, k'=tq+4)

            // B (x^T) fragments: n = batch, 4 n-tiles of 8 (already tf32)
            float2 bvf[4];
            #pragma unroll
            for (int j = 0; j < 4; j++)
                bvf[j] = *reinterpret_cast<const float2*>(&xs[(j * 8 + g) * RS + kp]);

            #pragma unroll
            for (int j = 0; j < 4; j++)
                MMA_TF32(acc[j], A0, A1, A2, A3,
                         __float_as_uint(bvf[j].x), __float_as_uint(bvf[j].y));
        }

        __syncthreads();                      // all reads of buf done
        if (c + NSTAGE < NCHUNK) stage(c % NSTAGE, c + NSTAGE);
    }

    // Epilogue: bias + exact GELU, store transposed into [batch][F_OUT]
    {
        const int r0 = mb + warp * 16 + g;             // output feature index
        const float bia0 = bias[r0];
        const float bia1 = bias[r0 + 8];
        #pragma unroll
        for (int j = 0; j < 4; j++) {
            const int bt = j * 8 + 2 * tq;             // batch index
            out[(size_t)bt       * F_OUT + r0    ] = gelu_exact(acc[j][0] + bia0);
            out[(size_t)(bt + 1) * F_OUT + r0    ] = gelu_exact(acc[j][1] + bia0);
            out[(size_t)bt       * F_OUT + r0 + 8] = gelu_exact(acc[j][2] + bia1);
            out[(size_t)(bt + 1) * F_OUT + r0 + 8] = gelu_exact(acc[j][3] + bia1);
        }
    }
}

// ---------------------------------------------------------------------------
// Kernel 2: softmax denominators over the HEADS axis (bias cancels).
// rZt[b][j][i] = 1 / sum_h exp(c * q[b,h,i] * k[b,h,j])
// One-shot staging (k full 64KB + q slice 16KB), barrier-free 512-h loop.
// ---------------------------------------------------------------------------
#define ATTN_SCALE 0.17677669529663687f   // 1/sqrt(32)
#define Z_SMEM (512 * 8 * 4 + 512 * 32 * 4)   // 81920 B

__global__ void attn_z_kernel() {
    extern __shared__ float zsm[];
    float* qs = zsm;              // [512][8]
    float* ks = zsm + 512 * 8;    // [512][32]

    const int b  = blockIdx.x;
    const int iq = blockIdx.y;
    const int tid = threadIdx.x;
    const int il  = tid >> 5;
    const int j   = tid & 31;
    const int i   = iq * 8 + il;

    const float4* __restrict__ qb4 = (const float4*)(g_q + (size_t)b * F_OUT);
    const float4* __restrict__ kb4 = (const float4*)(g_k + (size_t)b * F_OUT);

    // ks = k[b] verbatim (same layout): 4096 float4
    #pragma unroll
    for (int r = 0; r < 16; r++) {
        int idx = tid + r * 256;
        ((float4*)ks)[idx] = kb4[idx];
    }
    // qs[h][0..7] = q[b][h*32 + iq*8 .. +8]: 1024 float4
    #pragma unroll
    for (int r = 0; r < 4; r++) {
        int idx = tid + r * 256;
        int h = idx >> 1, u = idx & 1;
        ((float4*)qs)[idx] = qb4[h * 8 + iq * 2 + u];
    }
    __syncthreads();

    float z = 0.0f;
    #pragma unroll 8
    for (int h = 0; h < 512; h++)
        z += __expf(ATTN_SCALE * qs[h * 8 + il] * ks[h * 32 + j]);

    g_rzt[(size_t)b * 1024 + j * 32 + i] = 1.0f / z;
}

// ---------------------------------------------------------------------------
// Kernel 3: out[b,h,i] = sum_j exp(c*q_i*k_j) * rZ[b,i,j] * v[b,h,j]
// (k,v) staged in SMEM as float2 (LDS.64 broadcast per j),
// rz tile staged in SMEM.
// ---------------------------------------------------------------------------
__global__ void attn_o_kernel(float* __restrict__ out) {
    __shared__ float2 kvs[8][32];
    __shared__ float  rzs[1024];

    const int b    = blockIdx.y;
    const int tid  = threadIdx.x;
    const int wl   = tid >> 5;
    const int lane = tid & 31;
    const int h    = blockIdx.x * 8 + wl;

    const size_t base = (size_t)b * F_OUT + (size_t)h * 32;

    {
        float kk = g_k[base + lane];
        float vv = g_v[base + lane];
        kvs[wl][lane] = make_float2(kk, vv);
        #pragma unroll
        for (int r = 0; r < 4; r++)
            rzs[tid + r * 256] = g_rzt[(size_t)b * 1024 + tid + r * 256];
    }
    const float qv = g_q[base + lane] * ATTN_SCALE;
    __syncthreads();

    float accv = 0.0f;
    #pragma unroll
    for (int j = 0; j < 32; j++) {
        float2 kv = kvs[wl][j];                 // LDS.64 broadcast
        accv += __expf(qv * kv.x) * kv.y * rzs[j * 32 + lane];
    }
    out[((size_t)b * HEADS + h) * 32 + lane] = accv;
}

// ---------------------------------------------------------------------------
extern "C" void kernel_launch(void* const* d_in, const int* in_sizes, int n_in,
                              void* d_out, int out_size) {
    const float* x  = (const float*)d_in[0];
    const float* Wq = (const float*)d_in[1];
    const float* bq = (const float*)d_in[2];
    const float* Wk = (const float*)d_in[3];
    const float* bk = (const float*)d_in[4];
    const float* Wv = (const float*)d_in[5];
    const float* bv = (const float*)d_in[6];
    // d_in[7] (tw): constant along softmax axis (heads) -> cancels; unused.
    (void)in_sizes; (void)n_in; (void)out_size;

    cudaFuncSetAttribute(qkv_gemm_kernel,
                         cudaFuncAttributeMaxDynamicSharedMemorySize, SMEM_BYTES);
    cudaFuncSetAttribute(attn_z_kernel,
                         cudaFuncAttributeMaxDynamicSharedMemorySize, Z_SMEM);

    round_x_kernel<<<256, 256>>>((const float4*)x);
    qkv_gemm_kernel<<<dim3(F_OUT / MT, 3), 256, SMEM_BYTES>>>(Wq, bq, Wk, bk, Wv, bv);
    attn_z_kernel<<<dim3(32, 4), 256, Z_SMEM>>>();
    attn_o_kernel<<<dim3(64, 32), 256>>>((float*)d_out);
}